// round 1
// baseline (speedup 1.0000x reference)
#include <cuda_runtime.h>

#define BB 2
#define NN 8192
#define CC 256
#define KK 40
#define MM (BB * NN)

// ---------------- scratch (no allocation allowed) ----------------
__device__ float g_q[MM * CC];
__device__ float g_k[MM * CC];
__device__ float g_v[MM * CC];
__device__ float g_attn[MM * CC];
__device__ float g_xsum[BB * CC];
__device__ float g_qsum[BB * CC];
__device__ float g_score[BB * NN];
__device__ int   g_selidx[BB * KK];
__device__ float g_sel[BB * KK * CC];
__device__ float g_T[BB * KK * CC];
__device__ float g_Pq[MM * KK];
__device__ float g_Pk[MM * KK];

// ---------------- zero accumulators (runs every launch) ----------------
__global__ void zero_kernel() {
    int i = blockIdx.x * 256 + threadIdx.x;
    if (i < BB * CC) g_xsum[i] = 0.f;
    if (i < BB * KK * CC) g_T[i] = 0.f;
}

// ---------------- xsum[b,c] = sum_n query[b,n,c] ----------------
__global__ void xsum_kernel(const float* __restrict__ x) {
    int b = blockIdx.x >> 5;     // 32 chunks per batch
    int chunk = blockIdx.x & 31; // 256 rows per chunk
    int c = threadIdx.x;
    const float* p = x + ((size_t)b * NN + (size_t)chunk * 256) * CC + c;
    float s = 0.f;
#pragma unroll 8
    for (int n = 0; n < 256; n++) s += p[(size_t)n * CC];
    atomicAdd(&g_xsum[b * CC + c], s);
}

// ---------------- qsum[b,c] = xsum[b]·Wq[c] + N*bq[c] ----------------
__global__ void qsum_kernel(const float* __restrict__ Wq, const float* __restrict__ bq) {
    int b = blockIdx.x, c = threadIdx.x;
    const float* xs = &g_xsum[b * CC];
    const float* w = Wq + (size_t)c * CC;
    float s = 0.f;
#pragma unroll 8
    for (int d = 0; d < CC; d++) s += xs[d] * w[d];
    g_qsum[b * CC + c] = s + (float)NN * bq[c];
}

// ---------------- SGEMM: out[m,n] = X[m,:]·W[n,:] + bias[n] (+resid) ----------------
// M=16384, N=256, K=256.  BM=BN=128, BK=16, 256 threads, 8x8 microtile.
__global__ __launch_bounds__(256) void sgemm_nt(
    const float* __restrict__ X, const float* __restrict__ W,
    const float* __restrict__ bias, const float* __restrict__ resid,
    float* __restrict__ out) {
    __shared__ float As[16][128];
    __shared__ float Bs[16][128];
    const int m0 = blockIdx.x * 128;
    const int n0 = blockIdx.y * 128;
    const int tid = threadIdx.x;
    const int tx = tid & 15;
    const int ty = tid >> 4;
    const int lr = tid >> 2;         // 0..63
    const int ls = (tid & 3) << 2;   // 0,4,8,12

    float acc[8][8];
#pragma unroll
    for (int i = 0; i < 8; i++)
#pragma unroll
        for (int j = 0; j < 8; j++) acc[i][j] = 0.f;

    for (int k0 = 0; k0 < CC; k0 += 16) {
        float4 a0 = *(const float4*)(X + (size_t)(m0 + lr) * CC + k0 + ls);
        float4 a1 = *(const float4*)(X + (size_t)(m0 + lr + 64) * CC + k0 + ls);
        float4 w0 = *(const float4*)(W + (size_t)(n0 + lr) * CC + k0 + ls);
        float4 w1 = *(const float4*)(W + (size_t)(n0 + lr + 64) * CC + k0 + ls);
        __syncthreads();
        As[ls + 0][lr] = a0.x; As[ls + 1][lr] = a0.y; As[ls + 2][lr] = a0.z; As[ls + 3][lr] = a0.w;
        As[ls + 0][lr + 64] = a1.x; As[ls + 1][lr + 64] = a1.y; As[ls + 2][lr + 64] = a1.z; As[ls + 3][lr + 64] = a1.w;
        Bs[ls + 0][lr] = w0.x; Bs[ls + 1][lr] = w0.y; Bs[ls + 2][lr] = w0.z; Bs[ls + 3][lr] = w0.w;
        Bs[ls + 0][lr + 64] = w1.x; Bs[ls + 1][lr + 64] = w1.y; Bs[ls + 2][lr + 64] = w1.z; Bs[ls + 3][lr + 64] = w1.w;
        __syncthreads();
#pragma unroll
        for (int kk = 0; kk < 16; kk++) {
            float a[8], b[8];
            *(float4*)&a[0] = *(const float4*)&As[kk][ty * 8];
            *(float4*)&a[4] = *(const float4*)&As[kk][ty * 8 + 4];
            *(float4*)&b[0] = *(const float4*)&Bs[kk][tx * 8];
            *(float4*)&b[4] = *(const float4*)&Bs[kk][tx * 8 + 4];
#pragma unroll
            for (int i = 0; i < 8; i++)
#pragma unroll
                for (int j = 0; j < 8; j++) acc[i][j] += a[i] * b[j];
        }
    }

    float bv[8];
    *(float4*)&bv[0] = *(const float4*)(bias + n0 + tx * 8);
    *(float4*)&bv[4] = *(const float4*)(bias + n0 + tx * 8 + 4);

#pragma unroll
    for (int i = 0; i < 8; i++) {
        size_t off = (size_t)(m0 + ty * 8 + i) * CC + n0 + tx * 8;
        float4 r0, r1;
        r0.x = acc[i][0] + bv[0]; r0.y = acc[i][1] + bv[1];
        r0.z = acc[i][2] + bv[2]; r0.w = acc[i][3] + bv[3];
        r1.x = acc[i][4] + bv[4]; r1.y = acc[i][5] + bv[5];
        r1.z = acc[i][6] + bv[6]; r1.w = acc[i][7] + bv[7];
        if (resid) {
            float4 q0 = *(const float4*)(resid + off);
            float4 q1 = *(const float4*)(resid + off + 4);
            r0.x += q0.x; r0.y += q0.y; r0.z += q0.z; r0.w += q0.w;
            r1.x += q1.x; r1.y += q1.y; r1.z += q1.z; r1.w += q1.w;
        }
        *(float4*)(out + off) = r0;
        *(float4*)(out + off + 4) = r1;
    }
}

// ---------------- score[b,m] = k[b,m]·qsum[b] / 16 ----------------
__global__ void score_kernel() {
    int warp = threadIdx.x >> 5, lane = threadIdx.x & 31;
    int row = blockIdx.x * 8 + warp;     // 0..16383
    int b = row >> 13;
    const float* kr = &g_k[(size_t)row * CC];
    const float* qs = &g_qsum[b * CC];
    float s = 0.f;
#pragma unroll
    for (int i = 0; i < 8; i++) s += kr[lane + 32 * i] * qs[lane + 32 * i];
#pragma unroll
    for (int o = 16; o; o >>= 1) s += __shfl_xor_sync(0xFFFFFFFFu, s, o);
    if (lane == 0) g_score[row] = s * (1.f / 16.f);
}

// ---------------- top-40 by rank counting (index tie-break == lax.top_k) ----------------
__global__ void topk_kernel() {
    __shared__ float s[NN];
    int b = blockIdx.x >> 5;
    int chunk = blockIdx.x & 31;
    const float* sc = &g_score[b * NN];
    for (int j = threadIdx.x; j < NN; j += 256) s[j] = sc[j];
    __syncthreads();
    int i = chunk * 256 + threadIdx.x;
    float my = s[i];
    int rank = 0;
    for (int j = 0; j < NN; j += 4) {
        float4 v = *(const float4*)&s[j];
        rank += (v.x > my) || (v.x == my && (j + 0) < i);
        rank += (v.y > my) || (v.y == my && (j + 1) < i);
        rank += (v.z > my) || (v.z == my && (j + 2) < i);
        rank += (v.w > my) || (v.w == my && (j + 3) < i);
    }
    if (rank < KK) g_selidx[b * KK + rank] = i;
}

// ---------------- gather selected keys ----------------
__global__ void gather_kernel() {
    int r = blockIdx.x;          // 0..B*KK-1
    int b = r / KK;
    int idx = g_selidx[r];
    g_sel[(size_t)r * CC + threadIdx.x] = g_k[((size_t)b * NN + idx) * CC + threadIdx.x];
}

// ---------------- P[row,:] = softmax(src[row]·sel^T / 16), warp per row ----------------
__global__ __launch_bounds__(256) void landmark_kernel(const float* __restrict__ src,
                                                       float* __restrict__ P) {
    __shared__ float sel_sh[KK * CC];   // 40 KB
    int tid = threadIdx.x;
    int row0 = blockIdx.x * 8;
    int b = row0 >> 13;                 // blocks never straddle batches (8 | 8192)
    const float* selg = &g_sel[(size_t)b * KK * CC];
    for (int i = tid * 4; i < KK * CC; i += 1024)
        *(float4*)&sel_sh[i] = *(const float4*)&selg[i];
    __syncthreads();

    int warp = tid >> 5, lane = tid & 31;
    int row = row0 + warp;
    const float* r = &src[(size_t)row * CC];
    float rv[8];
#pragma unroll
    for (int i = 0; i < 8; i++) rv[i] = r[lane + 32 * i];

    float lg[KK];
#pragma unroll
    for (int j = 0; j < KK; j++) {
        const float* sj = &sel_sh[j * CC];
        float s = 0.f;
#pragma unroll
        for (int i = 0; i < 8; i++) s += rv[i] * sj[lane + 32 * i];
#pragma unroll
        for (int o = 16; o; o >>= 1) s += __shfl_xor_sync(0xFFFFFFFFu, s, o);
        lg[j] = s;   // identical in all lanes after reduction
    }
    float mx = lg[0];
#pragma unroll
    for (int j = 1; j < KK; j++) mx = fmaxf(mx, lg[j]);
    float sum = 0.f;
#pragma unroll
    for (int j = 0; j < KK; j++) { lg[j] = __expf((lg[j] - mx) * (1.f / 16.f)); sum += lg[j]; }
    float inv = 1.f / sum;
    float* Pr = &P[(size_t)row * KK];
#pragma unroll
    for (int j = 0; j < KK; j++)
        if (lane == (j & 31)) Pr[j] = lg[j] * inv;   // constant reg index, single writer
}

// ---------------- T[b,j,c] += sum_n Pk[b,n,j] * v[b,n,c]  (split over n-chunks) ----------------
__global__ __launch_bounds__(256) void tacc_kernel() {
    __shared__ float P_sh[128 * KK];    // 20 KB
    int b = blockIdx.y;
    int n0 = blockIdx.x * 128;
    int c = threadIdx.x;
    const float* Pg = &g_Pk[((size_t)b * NN + n0) * KK];
    for (int i = c * 4; i < 128 * KK; i += 1024)
        *(float4*)&P_sh[i] = *(const float4*)&Pg[i];
    __syncthreads();
    float acc[KK];
#pragma unroll
    for (int j = 0; j < KK; j++) acc[j] = 0.f;
    const float* v = &g_v[((size_t)b * NN + n0) * CC + c];
    for (int n = 0; n < 128; n++) {
        float val = v[(size_t)n * CC];
        const float* pr = &P_sh[n * KK];
#pragma unroll
        for (int j = 0; j < KK; j += 4) {
            float4 p = *(const float4*)&pr[j];
            acc[j + 0] += p.x * val; acc[j + 1] += p.y * val;
            acc[j + 2] += p.z * val; acc[j + 3] += p.w * val;
        }
    }
    float* T = &g_T[(size_t)b * KK * CC + c];
#pragma unroll
    for (int j = 0; j < KK; j++) atomicAdd(&T[j * CC], acc[j]);
}

// ---------------- attn[b,n,c] = sum_j Pq[b,n,j] * T[b,j,c] ----------------
__global__ __launch_bounds__(256) void out_kernel() {
    __shared__ float P_sh[128 * KK];
    int b = blockIdx.y;
    int n0 = blockIdx.x * 128;
    int c = threadIdx.x;
    const float* Pg = &g_Pq[((size_t)b * NN + n0) * KK];
    for (int i = c * 4; i < 128 * KK; i += 1024)
        *(float4*)&P_sh[i] = *(const float4*)&Pg[i];
    float t[KK];
    const float* T = &g_T[(size_t)b * KK * CC + c];
#pragma unroll
    for (int j = 0; j < KK; j++) t[j] = T[j * CC];
    __syncthreads();
    float* o = &g_attn[((size_t)b * NN + n0) * CC + c];
    for (int n = 0; n < 128; n++) {
        const float* pr = &P_sh[n * KK];
        float s = 0.f;
#pragma unroll
        for (int j = 0; j < KK; j += 4) {
            float4 p = *(const float4*)&pr[j];
            s += p.x * t[j + 0] + p.y * t[j + 1] + p.z * t[j + 2] + p.w * t[j + 3];
        }
        o[(size_t)n * CC] = s;
    }
}

// ---------------- launch ----------------
extern "C" void kernel_launch(void* const* d_in, const int* in_sizes, int n_in,
                              void* d_out, int out_size) {
    (void)in_sizes; (void)n_in; (void)out_size;
    const float* query = (const float*)d_in[0];
    const float* Wq = (const float*)d_in[1];
    const float* bq = (const float*)d_in[2];
    const float* Wk = (const float*)d_in[3];
    const float* bk = (const float*)d_in[4];
    const float* Wv = (const float*)d_in[5];
    const float* bv = (const float*)d_in[6];
    const float* Wo = (const float*)d_in[7];
    const float* bo = (const float*)d_in[8];
    float* out = (float*)d_out;

    float *p_q, *p_k, *p_v, *p_attn;
    cudaGetSymbolAddress((void**)&p_q, g_q);
    cudaGetSymbolAddress((void**)&p_k, g_k);
    cudaGetSymbolAddress((void**)&p_v, g_v);
    cudaGetSymbolAddress((void**)&p_attn, g_attn);
    float *p_Pq, *p_Pk;
    cudaGetSymbolAddress((void**)&p_Pq, g_Pq);
    cudaGetSymbolAddress((void**)&p_Pk, g_Pk);

    zero_kernel<<<80, 256>>>();
    xsum_kernel<<<64, 256>>>(query);
    qsum_kernel<<<BB, 256>>>(Wq, bq);

    dim3 gg(MM / 128, CC / 128);
    sgemm_nt<<<gg, 256>>>(query, Wq, bq, nullptr, p_q);
    sgemm_nt<<<gg, 256>>>(query, Wk, bk, nullptr, p_k);
    sgemm_nt<<<gg, 256>>>(query, Wv, bv, nullptr, p_v);

    score_kernel<<<MM / 8, 256>>>();
    topk_kernel<<<BB * 32, 256>>>();
    gather_kernel<<<BB * KK, 256>>>();

    landmark_kernel<<<MM / 8, 256>>>(p_q, p_Pq);
    landmark_kernel<<<MM / 8, 256>>>(p_k, p_Pk);

    dim3 gt(NN / 128, BB);
    tacc_kernel<<<gt, 256>>>();
    out_kernel<<<gt, 256>>>();

    sgemm_nt<<<gg, 256>>>(p_attn, Wo, bo, query, out);
}

// round 3
// speedup vs baseline: 1.7549x; 1.7549x over previous
#include <cuda_runtime.h>
#include <cstdint>

#define BB 2
#define NN 8192
#define CC 256
#define KK 40
#define MM (BB * NN)

// ================= scratch =================
__device__ float g_q[MM * CC];
__device__ float g_k[MM * CC];
__device__ float g_v[MM * CC];
__device__ float g_attn[MM * CC];
__device__ float g_xsum[BB * CC];
__device__ float g_u[BB * CC];
__device__ float g_score[BB * NN];
__device__ int   g_selidx[BB * KK];
__device__ float g_sel[BB * KK * CC];
__device__ float g_T[BB * KK * CC];
__device__ float g_Pq[MM * KK];
__device__ float g_Pk[MM * KK];

// ================= mma helpers (family-portable PTX only) =================
__device__ __forceinline__ uint32_t f2tf32(float f) {
    uint32_t r;
    asm("cvt.rna.tf32.f32 %0, %1;" : "=r"(r) : "f"(f));
    return r;
}
__device__ __forceinline__ void mma8(float* c, const uint32_t* a, const uint32_t* b) {
    asm volatile(
        "mma.sync.aligned.m16n8k8.row.col.f32.tf32.tf32.f32 "
        "{%0,%1,%2,%3}, {%4,%5,%6,%7}, {%8,%9}, {%0,%1,%2,%3};"
        : "+f"(c[0]), "+f"(c[1]), "+f"(c[2]), "+f"(c[3])
        : "r"(a[0]), "r"(a[1]), "r"(a[2]), "r"(a[3]), "r"(b[0]), "r"(b[1]));
}

// ================= small kernels =================
__global__ void zero_kernel() {
    int i = blockIdx.x * 256 + threadIdx.x;
    if (i < BB * CC) g_xsum[i] = 0.f;
    if (i < BB * KK * CC) g_T[i] = 0.f;
}

__global__ void xsum_kernel(const float* __restrict__ x) {
    int b = blockIdx.x >> 5;
    int chunk = blockIdx.x & 31;
    int c = threadIdx.x;
    const float* p = x + ((size_t)b * NN + (size_t)chunk * 256) * CC + c;
    float s = 0.f;
#pragma unroll 8
    for (int n = 0; n < 256; n++) s += p[(size_t)n * CC];
    atomicAdd(&g_xsum[b * CC + c], s);
}

// qsum = Wq*xsum + N*bq (fp32 exact), then u = Wk^T * qsum
__global__ void prep_kernel(const float* __restrict__ Wq, const float* __restrict__ bq,
                            const float* __restrict__ Wk) {
    __shared__ float qs[CC];
    int b = blockIdx.x, tid = threadIdx.x, w = tid >> 5, lane = tid & 31;
    const float* xs = &g_xsum[b * CC];
    for (int c = w * 32; c < w * 32 + 32; c++) {
        const float* wr = Wq + (size_t)c * CC;
        float s = 0.f;
#pragma unroll
        for (int i = 0; i < 8; i++) s += xs[lane + 32 * i] * wr[lane + 32 * i];
#pragma unroll
        for (int o = 16; o; o >>= 1) s += __shfl_xor_sync(0xFFFFFFFFu, s, o);
        if (lane == 0) qs[c] = s + (float)NN * bq[c];
    }
    __syncthreads();
    int c = tid;
    float u = 0.f;
#pragma unroll 8
    for (int d = 0; d < CC; d++) u += qs[d] * Wk[(size_t)d * CC + c];
    g_u[b * CC + c] = u;
}

// score_m = u_b . x_m  (order-identical to qsum.k_m/16 up to a constant; exact fp32)
__global__ void score_kernel(const float* __restrict__ x) {
    int warp = threadIdx.x >> 5, lane = threadIdx.x & 31;
    int row = blockIdx.x * 8 + warp;
    int b = row >> 13;
    const float* xr = x + (size_t)row * CC;
    const float* u = &g_u[b * CC];
    float s = 0.f;
#pragma unroll
    for (int i = 0; i < 8; i++) s += xr[lane + 32 * i] * u[lane + 32 * i];
#pragma unroll
    for (int o = 16; o; o >>= 1) s += __shfl_xor_sync(0xFFFFFFFFu, s, o);
    if (lane == 0) g_score[row] = s;
}

__global__ void topk_kernel() {
    __shared__ float s[NN];
    int b = blockIdx.x >> 5;
    int chunk = blockIdx.x & 31;
    const float* sc = &g_score[b * NN];
    for (int j = threadIdx.x; j < NN; j += 256) s[j] = sc[j];
    __syncthreads();
    int i = chunk * 256 + threadIdx.x;
    float my = s[i];
    int rank = 0;
    for (int j = 0; j < NN; j += 4) {
        float4 v = *(const float4*)&s[j];
        rank += (v.x > my) || (v.x == my && (j + 0) < i);
        rank += (v.y > my) || (v.y == my && (j + 1) < i);
        rank += (v.z > my) || (v.z == my && (j + 2) < i);
        rank += (v.w > my) || (v.w == my && (j + 3) < i);
    }
    if (rank < KK) g_selidx[b * KK + rank] = i;
}

__global__ void gather_kernel() {
    int r = blockIdx.x;
    int b = r / KK;
    int idx = g_selidx[r];
    g_sel[(size_t)r * CC + threadIdx.x] = g_k[((size_t)b * NN + idx) * CC + threadIdx.x];
}

// ================= tf32 mma GEMM: out[m,n] = X[m,:].W[n,:] + bias[n] (+resid) =================
// BM=128, BN=128, BK=32, 256 threads, warp tile 64x32 (2x4 warp grid).
// smem u32 offsets (stride 36 for conflict-free scalar LDS of fragments):
#define GA0 0u
#define GA1 4608u
#define GB0 9216u
#define GB1 13824u
#define G_SMEM (18432u * 4u)

__global__ __launch_bounds__(256) void gemm_mma(
    const float* __restrict__ X,
    const float* __restrict__ W0, const float* __restrict__ W1, const float* __restrict__ W2,
    const float* __restrict__ B0, const float* __restrict__ B1, const float* __restrict__ B2,
    const float* __restrict__ resid,
    float* __restrict__ O0, float* __restrict__ O1, float* __restrict__ O2) {
    extern __shared__ __align__(16) uint32_t sm[];
    const int z = blockIdx.z;
    const float* W = (z == 0) ? W0 : (z == 1) ? W1 : W2;
    const float* bias = (z == 0) ? B0 : (z == 1) ? B1 : B2;
    float* out = (z == 0) ? O0 : (z == 1) ? O1 : O2;

    const int tid = threadIdx.x, lane = tid & 31, wid = tid >> 5;
    const int m0 = blockIdx.x * 128;
    const int n0 = blockIdx.y * 128;
    const int wm = wid & 1, wn = wid >> 1;

    float c[4][4][4];
#pragma unroll
    for (int mf = 0; mf < 4; mf++)
#pragma unroll
        for (int nf = 0; nf < 4; nf++)
#pragma unroll
            for (int j = 0; j < 4; j++) c[mf][nf][j] = 0.f;

    const int rowL = tid >> 1;            // not used; keep simple idx math below
    (void)rowL;

    float4 av[4], bv[4];
    // prefetch chunk 0
#pragma unroll
    for (int i = 0; i < 4; i++) {
        int idx = tid + i * 256;
        int r = idx >> 3, c4 = idx & 7;
        av[i] = *(const float4*)(X + (size_t)(m0 + r) * CC + c4 * 4);
        bv[i] = *(const float4*)(W + (size_t)(n0 + r) * CC + c4 * 4);
    }
#pragma unroll
    for (int i = 0; i < 4; i++) {
        int idx = tid + i * 256;
        int r = idx >> 3, c4 = idx & 7;
        uint4 ta = make_uint4(f2tf32(av[i].x), f2tf32(av[i].y), f2tf32(av[i].z), f2tf32(av[i].w));
        uint4 tb = make_uint4(f2tf32(bv[i].x), f2tf32(bv[i].y), f2tf32(bv[i].z), f2tf32(bv[i].w));
        *(uint4*)&sm[GA0 + r * 36 + c4 * 4] = ta;
        *(uint4*)&sm[GB0 + r * 36 + c4 * 4] = tb;
    }
    __syncthreads();

    for (int ch = 0; ch < 8; ch++) {
        if (ch < 7) {
            int k0 = (ch + 1) * 32;
#pragma unroll
            for (int i = 0; i < 4; i++) {
                int idx = tid + i * 256;
                int r = idx >> 3, c4 = idx & 7;
                av[i] = *(const float4*)(X + (size_t)(m0 + r) * CC + k0 + c4 * 4);
                bv[i] = *(const float4*)(W + (size_t)(n0 + r) * CC + k0 + c4 * 4);
            }
        }
        const uint32_t Ab = (ch & 1) ? GA1 : GA0;
        const uint32_t Bb = (ch & 1) ? GB1 : GB0;
        const uint32_t abase = Ab + (wm * 64 + (lane >> 2)) * 36 + (lane & 3);
        const uint32_t bbase = Bb + (wn * 32 + (lane >> 2)) * 36 + (lane & 3);
#pragma unroll
        for (int ks = 0; ks < 4; ks++) {
            const int k = ks * 8;
            uint32_t a[4][4], b[4][2];
#pragma unroll
            for (int mf = 0; mf < 4; mf++) {
                a[mf][0] = sm[abase + mf * 576 + k];
                a[mf][1] = sm[abase + mf * 576 + 288 + k];
                a[mf][2] = sm[abase + mf * 576 + k + 4];
                a[mf][3] = sm[abase + mf * 576 + 288 + k + 4];
            }
#pragma unroll
            for (int nf = 0; nf < 4; nf++) {
                b[nf][0] = sm[bbase + nf * 288 + k];
                b[nf][1] = sm[bbase + nf * 288 + k + 4];
            }
#pragma unroll
            for (int mf = 0; mf < 4; mf++)
#pragma unroll
                for (int nf = 0; nf < 4; nf++) mma8(c[mf][nf], a[mf], b[nf]);
        }
        if (ch < 7) {
            const uint32_t An = (ch & 1) ? GA0 : GA1;
            const uint32_t Bn = (ch & 1) ? GB0 : GB1;
#pragma unroll
            for (int i = 0; i < 4; i++) {
                int idx = tid + i * 256;
                int r = idx >> 3, c4 = idx & 7;
                uint4 ta = make_uint4(f2tf32(av[i].x), f2tf32(av[i].y), f2tf32(av[i].z), f2tf32(av[i].w));
                uint4 tb = make_uint4(f2tf32(bv[i].x), f2tf32(bv[i].y), f2tf32(bv[i].z), f2tf32(bv[i].w));
                *(uint4*)&sm[An + r * 36 + c4 * 4] = ta;
                *(uint4*)&sm[Bn + r * 36 + c4 * 4] = tb;
            }
            __syncthreads();
        }
    }

    // epilogue
#pragma unroll
    for (int nf = 0; nf < 4; nf++) {
        const int col = n0 + wn * 32 + nf * 8 + 2 * (lane & 3);
        const float bi0 = bias[col], bi1 = bias[col + 1];
#pragma unroll
        for (int mf = 0; mf < 4; mf++) {
            const int row = m0 + wm * 64 + mf * 16 + (lane >> 2);
            size_t o0 = (size_t)row * CC + col;
            size_t o1 = (size_t)(row + 8) * CC + col;
            float2 v0, v1;
            v0.x = c[mf][nf][0] + bi0; v0.y = c[mf][nf][1] + bi1;
            v1.x = c[mf][nf][2] + bi0; v1.y = c[mf][nf][3] + bi1;
            if (resid) {
                float2 r0 = *(const float2*)(resid + o0);
                float2 r1 = *(const float2*)(resid + o1);
                v0.x += r0.x; v0.y += r0.y;
                v1.x += r1.x; v1.y += r1.y;
            }
            *(float2*)(out + o0) = v0;
            *(float2*)(out + o1) = v1;
        }
    }
}

// ================= landmark softmax via mma: P = softmax(src.sel^T/16) =================
// grid (128, 2): y picks (src,P) = (q,Pq) or (k,Pk). 128 rows per CTA, 8 warps (16 rows each).
#define LSEL 0u
#define LA0 10720u
#define LA1 15328u
#define L_SMEM (19936u * 4u)

__global__ __launch_bounds__(256) void lm_mma() {
    extern __shared__ __align__(16) uint32_t sm[];
    const int tid = threadIdx.x, lane = tid & 31, wid = tid >> 5;
    const int m0 = blockIdx.x * 128;
    const int b = m0 >> 13;
    const float* src = blockIdx.y ? g_k : g_q;
    float* P = blockIdx.y ? g_Pk : g_Pq;
    const float* selg = &g_sel[(size_t)b * KK * CC];

    // load sel (40x256) into smem, stride 268
#pragma unroll
    for (int i = 0; i < 10; i++) {
        int idx = tid + i * 256;
        int r = idx >> 6, c4 = idx & 63;
        float4 v = *(const float4*)(selg + (size_t)r * CC + c4 * 4);
        uint4 t4 = make_uint4(f2tf32(v.x), f2tf32(v.y), f2tf32(v.z), f2tf32(v.w));
        *(uint4*)&sm[LSEL + r * 268 + c4 * 4] = t4;
    }
    // prefetch A chunk 0
    float4 av[4];
#pragma unroll
    for (int i = 0; i < 4; i++) {
        int idx = tid + i * 256;
        int r = idx >> 3, c4 = idx & 7;
        av[i] = *(const float4*)(src + (size_t)(m0 + r) * CC + c4 * 4);
    }
#pragma unroll
    for (int i = 0; i < 4; i++) {
        int idx = tid + i * 256;
        int r = idx >> 3, c4 = idx & 7;
        uint4 t4 = make_uint4(f2tf32(av[i].x), f2tf32(av[i].y), f2tf32(av[i].z), f2tf32(av[i].w));
        *(uint4*)&sm[LA0 + r * 36 + c4 * 4] = t4;
    }
    __syncthreads();

    float c[5][4];
#pragma unroll
    for (int nf = 0; nf < 5; nf++)
#pragma unroll
        for (int j = 0; j < 4; j++) c[nf][j] = 0.f;

    for (int ch = 0; ch < 8; ch++) {
        if (ch < 7) {
            int k0 = (ch + 1) * 32;
#pragma unroll
            for (int i = 0; i < 4; i++) {
                int idx = tid + i * 256;
                int r = idx >> 3, c4 = idx & 7;
                av[i] = *(const float4*)(src + (size_t)(m0 + r) * CC + k0 + c4 * 4);
            }
        }
        const uint32_t Ab = (ch & 1) ? LA1 : LA0;
        const uint32_t abase = Ab + (wid * 16 + (lane >> 2)) * 36 + (lane & 3);
        const uint32_t sbase = LSEL + (lane >> 2) * 268 + ch * 32 + (lane & 3);
#pragma unroll
        for (int ks = 0; ks < 4; ks++) {
            const int k = ks * 8;
            uint32_t a[4], bfr[5][2];
            a[0] = sm[abase + k];
            a[1] = sm[abase + 288 + k];
            a[2] = sm[abase + k + 4];
            a[3] = sm[abase + 288 + k + 4];
#pragma unroll
            for (int nf = 0; nf < 5; nf++) {
                bfr[nf][0] = sm[sbase + nf * 8 * 268 + k];
                bfr[nf][1] = sm[sbase + nf * 8 * 268 + k + 4];
            }
#pragma unroll
            for (int nf = 0; nf < 5; nf++) mma8(c[nf], a, bfr[nf]);
        }
        if (ch < 7) {
            const uint32_t An = (ch & 1) ? LA0 : LA1;
#pragma unroll
            for (int i = 0; i < 4; i++) {
                int idx = tid + i * 256;
                int r = idx >> 3, c4 = idx & 7;
                uint4 t4 = make_uint4(f2tf32(av[i].x), f2tf32(av[i].y), f2tf32(av[i].z), f2tf32(av[i].w));
                *(uint4*)&sm[An + r * 36 + c4 * 4] = t4;
            }
            __syncthreads();
        }
    }

    // softmax epilogue: rows r0 = m0 + wid*16 + (lane>>2), r1 = r0+8
    float v0[10], v1[10];
#pragma unroll
    for (int nf = 0; nf < 5; nf++) {
        v0[nf * 2] = c[nf][0]; v0[nf * 2 + 1] = c[nf][1];
        v1[nf * 2] = c[nf][2]; v1[nf * 2 + 1] = c[nf][3];
    }
    float mx0 = v0[0], mx1 = v1[0];
#pragma unroll
    for (int i = 1; i < 10; i++) { mx0 = fmaxf(mx0, v0[i]); mx1 = fmaxf(mx1, v1[i]); }
    mx0 = fmaxf(mx0, __shfl_xor_sync(0xFFFFFFFFu, mx0, 1));
    mx0 = fmaxf(mx0, __shfl_xor_sync(0xFFFFFFFFu, mx0, 2));
    mx1 = fmaxf(mx1, __shfl_xor_sync(0xFFFFFFFFu, mx1, 1));
    mx1 = fmaxf(mx1, __shfl_xor_sync(0xFFFFFFFFu, mx1, 2));
    float s0 = 0.f, s1 = 0.f;
#pragma unroll
    for (int i = 0; i < 10; i++) {
        v0[i] = __expf((v0[i] - mx0) * 0.0625f); s0 += v0[i];
        v1[i] = __expf((v1[i] - mx1) * 0.0625f); s1 += v1[i];
    }
    s0 += __shfl_xor_sync(0xFFFFFFFFu, s0, 1);
    s0 += __shfl_xor_sync(0xFFFFFFFFu, s0, 2);
    s1 += __shfl_xor_sync(0xFFFFFFFFu, s1, 1);
    s1 += __shfl_xor_sync(0xFFFFFFFFu, s1, 2);
    const float i0 = 1.f / s0, i1 = 1.f / s1;
    const int r0 = m0 + wid * 16 + (lane >> 2);
#pragma unroll
    for (int nf = 0; nf < 5; nf++) {
        int col = nf * 8 + 2 * (lane & 3);
        float2 w0, w1;
        w0.x = v0[nf * 2] * i0; w0.y = v0[nf * 2 + 1] * i0;
        w1.x = v1[nf * 2] * i1; w1.y = v1[nf * 2 + 1] * i1;
        *(float2*)&P[(size_t)r0 * KK + col] = w0;
        *(float2*)&P[(size_t)(r0 + 8) * KK + col] = w1;
    }
}

// ================= T accumulate / output product =================
__global__ __launch_bounds__(256) void tacc_kernel() {
    __shared__ float P_sh[128 * KK];
    int b = blockIdx.y;
    int n0 = blockIdx.x * 128;
    int c = threadIdx.x;
    const float* Pg = &g_Pk[((size_t)b * NN + n0) * KK];
    for (int i = c * 4; i < 128 * KK; i += 1024)
        *(float4*)&P_sh[i] = *(const float4*)&Pg[i];
    __syncthreads();
    float acc[KK];
#pragma unroll
    for (int j = 0; j < KK; j++) acc[j] = 0.f;
    const float* v = &g_v[((size_t)b * NN + n0) * CC + c];
    for (int n = 0; n < 128; n++) {
        float val = v[(size_t)n * CC];
        const float* pr = &P_sh[n * KK];
#pragma unroll
        for (int j = 0; j < KK; j += 4) {
            float4 p = *(const float4*)&pr[j];
            acc[j + 0] += p.x * val; acc[j + 1] += p.y * val;
            acc[j + 2] += p.z * val; acc[j + 3] += p.w * val;
        }
    }
    float* T = &g_T[(size_t)b * KK * CC + c];
#pragma unroll
    for (int j = 0; j < KK; j++) atomicAdd(&T[j * CC], acc[j]);
}

__global__ __launch_bounds__(256) void out_kernel() {
    __shared__ float P_sh[128 * KK];
    int b = blockIdx.y;
    int n0 = blockIdx.x * 128;
    int c = threadIdx.x;
    const float* Pg = &g_Pq[((size_t)b * NN + n0) * KK];
    for (int i = c * 4; i < 128 * KK; i += 1024)
        *(float4*)&P_sh[i] = *(const float4*)&Pg[i];
    float t[KK];
    const float* T = &g_T[(size_t)b * KK * CC + c];
#pragma unroll
    for (int j = 0; j < KK; j++) t[j] = T[j * CC];
    __syncthreads();
    float* o = &g_attn[((size_t)b * NN + n0) * CC + c];
    for (int n = 0; n < 128; n++) {
        const float* pr = &P_sh[n * KK];
        float s = 0.f;
#pragma unroll
        for (int j = 0; j < KK; j += 4) {
            float4 p = *(const float4*)&pr[j];
            s += p.x * t[j + 0] + p.y * t[j + 1] + p.z * t[j + 2] + p.w * t[j + 3];
        }
        o[(size_t)n * CC] = s;
    }
}

// ================= launch =================
extern "C" void kernel_launch(void* const* d_in, const int* in_sizes, int n_in,
                              void* d_out, int out_size) {
    (void)in_sizes; (void)n_in; (void)out_size;
    const float* query = (const float*)d_in[0];
    const float* Wq = (const float*)d_in[1];
    const float* bq = (const float*)d_in[2];
    const float* Wk = (const float*)d_in[3];
    const float* bk = (const float*)d_in[4];
    const float* Wv = (const float*)d_in[5];
    const float* bv = (const float*)d_in[6];
    const float* Wo = (const float*)d_in[7];
    const float* bo = (const float*)d_in[8];
    float* out = (float*)d_out;

    cudaFuncSetAttribute(gemm_mma, cudaFuncAttributeMaxDynamicSharedMemorySize, G_SMEM);
    cudaFuncSetAttribute(lm_mma, cudaFuncAttributeMaxDynamicSharedMemorySize, L_SMEM);

    float *p_q, *p_k, *p_v, *p_attn;
    cudaGetSymbolAddress((void**)&p_q, g_q);
    cudaGetSymbolAddress((void**)&p_k, g_k);
    cudaGetSymbolAddress((void**)&p_v, g_v);
    cudaGetSymbolAddress((void**)&p_attn, g_attn);

    zero_kernel<<<80, 256>>>();
    xsum_kernel<<<64, 256>>>(query);
    prep_kernel<<<BB, 256>>>(Wq, bq, Wk);
    score_kernel<<<MM / 8, 256>>>(query);
    topk_kernel<<<BB * 32, 256>>>();

    // fused q/k/v projections
    dim3 gqkv(MM / 128, CC / 128, 3);
    gemm_mma<<<gqkv, 256, G_SMEM>>>(query, Wq, Wk, Wv, bq, bk, bv, nullptr, p_q, p_k, p_v);

    gather_kernel<<<BB * KK, 256>>>();

    // fused landmark softmax for q and k
    lm_mma<<<dim3(MM / 128, 2), 256, L_SMEM>>>();

    dim3 gt(NN / 128, BB);
    tacc_kernel<<<gt, 256>>>();
    out_kernel<<<gt, 256>>>();

    // output projection + residual
    dim3 go(MM / 128, CC / 128, 1);
    gemm_mma<<<go, 256, G_SMEM>>>(p_attn, Wo, Wo, Wo, bo, bo, bo, query, out, out, out);
}

// round 4
// speedup vs baseline: 2.0280x; 1.1557x over previous
#include <cuda_runtime.h>
#include <cuda_fp16.h>
#include <cstdint>

#define BB 2
#define NN 8192
#define CC 256
#define KK 40
#define MM (BB * NN)

// ================= scratch =================
__device__ float g_q[MM * CC];
__device__ float g_k[MM * CC];
__device__ float g_v[MM * CC];
__device__ float g_attn[MM * CC];
__device__ float g_part[BB * 32 * CC];
__device__ float g_u[BB * CC];
__device__ float g_score[BB * NN];
__device__ int   g_selidx[BB * KK];
__device__ float g_T[BB * KK * CC];
__device__ float g_Pq[MM * KK];
__device__ float g_Pk[MM * KK];

// ================= helpers (family-portable PTX only) =================
__device__ __forceinline__ uint32_t pk2(float lo, float hi) {
    __half2 h = __floats2half2_rn(lo, hi);
    return *reinterpret_cast<uint32_t*>(&h);
}
__device__ __forceinline__ void mma16(float* c, const uint32_t* a, const uint32_t* b) {
    asm volatile(
        "mma.sync.aligned.m16n8k16.row.col.f32.f16.f16.f32 "
        "{%0,%1,%2,%3}, {%4,%5,%6,%7}, {%8,%9}, {%0,%1,%2,%3};"
        : "+f"(c[0]), "+f"(c[1]), "+f"(c[2]), "+f"(c[3])
        : "r"(a[0]), "r"(a[1]), "r"(a[2]), "r"(a[3]), "r"(b[0]), "r"(b[1]));
}

// ================= xsum: per-chunk partial column sums + zero g_T =================
// grid 64 = (b<<5)|chunk, each block sums 256 rows into g_part[b*32+chunk][:]
__global__ __launch_bounds__(256) void xsum_kernel(const float* __restrict__ x) {
    __shared__ float4 red[4][64];
    int b = blockIdx.x >> 5, chunk = blockIdx.x & 31;
    int c4 = threadIdx.x & 63, rl = threadIdx.x >> 6;
    const float* base = x + ((size_t)b * NN + chunk * 256 + rl) * CC + c4 * 4;
    float4 s = make_float4(0.f, 0.f, 0.f, 0.f);
#pragma unroll 8
    for (int n = 0; n < 64; n++) {
        float4 v = *(const float4*)(base + (size_t)n * 4 * CC);
        s.x += v.x; s.y += v.y; s.z += v.z; s.w += v.w;
    }
    red[rl][c4] = s;
    // fold in g_T zeroing (consumed much later by tacc)
    for (int i = blockIdx.x * 256 + threadIdx.x; i < BB * KK * CC; i += 64 * 256)
        g_T[i] = 0.f;
    __syncthreads();
    if (rl == 0) {
        float4 a = red[0][c4], b2 = red[1][c4], c2 = red[2][c4], d = red[3][c4];
        float4 o;
        o.x = a.x + b2.x + c2.x + d.x; o.y = a.y + b2.y + c2.y + d.y;
        o.z = a.z + b2.z + c2.z + d.z; o.w = a.w + b2.w + c2.w + d.w;
        *(float4*)&g_part[(size_t)(b * 32 + chunk) * CC + c4 * 4] = o;
    }
}

// qsum = Wq*xsum + N*bq (fp32 exact), then u = Wk^T * qsum
__global__ void prep_kernel(const float* __restrict__ Wq, const float* __restrict__ bq,
                            const float* __restrict__ Wk) {
    __shared__ float xs[CC], qs[CC];
    int b = blockIdx.x, tid = threadIdx.x, w = tid >> 5, lane = tid & 31;
    float sx = 0.f;
#pragma unroll 8
    for (int ch = 0; ch < 32; ch++) sx += g_part[(size_t)(b * 32 + ch) * CC + tid];
    xs[tid] = sx;
    __syncthreads();
    for (int c = w * 32; c < w * 32 + 32; c++) {
        const float* wr = Wq + (size_t)c * CC;
        float s = 0.f;
#pragma unroll
        for (int i = 0; i < 8; i++) s += xs[lane + 32 * i] * wr[lane + 32 * i];
#pragma unroll
        for (int o = 16; o; o >>= 1) s += __shfl_xor_sync(0xFFFFFFFFu, s, o);
        if (lane == 0) qs[c] = s + (float)NN * bq[c];
    }
    __syncthreads();
    int c = tid;
    float u = 0.f;
#pragma unroll 8
    for (int d = 0; d < CC; d++) u += qs[d] * Wk[(size_t)d * CC + c];
    g_u[b * CC + c] = u;
}

// score_m = u_b . x_m  (order-identical to qsum.k_m/16 up to constant; exact fp32)
__global__ void score_kernel(const float* __restrict__ x) {
    int warp = threadIdx.x >> 5, lane = threadIdx.x & 31;
    int row = blockIdx.x * 8 + warp;
    int b = row >> 13;
    const float4* xr = (const float4*)(x + (size_t)row * CC);
    const float4* u = (const float4*)(&g_u[b * CC]);
    float4 v0 = xr[lane], v1 = xr[lane + 32];
    float4 u0 = u[lane], u1 = u[lane + 32];
    float s = v0.x * u0.x + v0.y * u0.y + v0.z * u0.z + v0.w * u0.w
            + v1.x * u1.x + v1.y * u1.y + v1.z * u1.z + v1.w * u1.w;
#pragma unroll
    for (int o = 16; o; o >>= 1) s += __shfl_xor_sync(0xFFFFFFFFu, s, o);
    if (lane == 0) g_score[row] = s;
}

__global__ void topk_kernel() {
    __shared__ float s[NN];
    int b = blockIdx.x >> 5;
    int chunk = blockIdx.x & 31;
    const float* sc = &g_score[b * NN];
    for (int j = threadIdx.x; j < NN; j += 256) s[j] = sc[j];
    __syncthreads();
    int i = chunk * 256 + threadIdx.x;
    float my = s[i];
    int rank = 0;
    for (int j = 0; j < NN; j += 4) {
        float4 v = *(const float4*)&s[j];
        rank += (v.x > my) || (v.x == my && (j + 0) < i);
        rank += (v.y > my) || (v.y == my && (j + 1) < i);
        rank += (v.z > my) || (v.z == my && (j + 2) < i);
        rank += (v.w > my) || (v.w == my && (j + 3) < i);
    }
    if (rank < KK) g_selidx[b * KK + rank] = i;
}

// ================= fp16 mma GEMM: out[m,n] = X[m,:].W[n,:] + bias[n] (+resid) =================
// BM=128, BN=128, BK=32 f32 (16 f16x2 kpairs), 256 threads, warp tile 64x32.
// smem rows stride 20 u32 (16 kpairs + 4 pad) -> conflict-free fragment LDS.
#define GA0 0u
#define GA1 2560u
#define GB0 5120u
#define GB1 7680u
#define G_SMEM (10240u * 4u)

__global__ __launch_bounds__(256) void gemm_mma(
    const float* __restrict__ X,
    const float* __restrict__ W0, const float* __restrict__ W1, const float* __restrict__ W2,
    const float* __restrict__ B0, const float* __restrict__ B1, const float* __restrict__ B2,
    const float* __restrict__ resid,
    float* __restrict__ O0, float* __restrict__ O1, float* __restrict__ O2) {
    extern __shared__ __align__(16) uint32_t sm[];
    const int z = blockIdx.z;
    const float* W = (z == 0) ? W0 : (z == 1) ? W1 : W2;
    const float* bias = (z == 0) ? B0 : (z == 1) ? B1 : B2;
    float* out = (z == 0) ? O0 : (z == 1) ? O1 : O2;

    const int tid = threadIdx.x, lane = tid & 31, wid = tid >> 5;
    const int m0 = blockIdx.x * 128;
    const int n0 = blockIdx.y * 128;
    const int wm = wid & 1, wn = wid >> 1;

    float c[4][4][4];
#pragma unroll
    for (int mf = 0; mf < 4; mf++)
#pragma unroll
        for (int nf = 0; nf < 4; nf++)
#pragma unroll
            for (int j = 0; j < 4; j++) c[mf][nf][j] = 0.f;

    float4 av[4], bv[4];
#pragma unroll
    for (int i = 0; i < 4; i++) {
        int idx = tid + i * 256;
        int r = idx >> 3, c4 = idx & 7;
        av[i] = *(const float4*)(X + (size_t)(m0 + r) * CC + c4 * 4);
        bv[i] = *(const float4*)(W + (size_t)(n0 + r) * CC + c4 * 4);
    }
#pragma unroll
    for (int i = 0; i < 4; i++) {
        int idx = tid + i * 256;
        int r = idx >> 3, c4 = idx & 7;
        uint2 ha = make_uint2(pk2(av[i].x, av[i].y), pk2(av[i].z, av[i].w));
        uint2 hb = make_uint2(pk2(bv[i].x, bv[i].y), pk2(bv[i].z, bv[i].w));
        *(uint2*)&sm[GA0 + r * 20 + c4 * 2] = ha;
        *(uint2*)&sm[GB0 + r * 20 + c4 * 2] = hb;
    }
    __syncthreads();

    for (int ch = 0; ch < 8; ch++) {
        if (ch < 7) {
            int k0 = (ch + 1) * 32;
#pragma unroll
            for (int i = 0; i < 4; i++) {
                int idx = tid + i * 256;
                int r = idx >> 3, c4 = idx & 7;
                av[i] = *(const float4*)(X + (size_t)(m0 + r) * CC + k0 + c4 * 4);
                bv[i] = *(const float4*)(W + (size_t)(n0 + r) * CC + k0 + c4 * 4);
            }
        }
        const uint32_t Ab = (ch & 1) ? GA1 : GA0;
        const uint32_t Bb = (ch & 1) ? GB1 : GB0;
#pragma unroll
        for (int s = 0; s < 2; s++) {
            const uint32_t abase = Ab + (wm * 64 + (lane >> 2)) * 20 + (lane & 3) + s * 8;
            const uint32_t bbase = Bb + (wn * 32 + (lane >> 2)) * 20 + (lane & 3) + s * 8;
            uint32_t a[4][4], b[4][2];
#pragma unroll
            for (int mf = 0; mf < 4; mf++) {
                a[mf][0] = sm[abase + mf * 320];
                a[mf][1] = sm[abase + mf * 320 + 160];
                a[mf][2] = sm[abase + mf * 320 + 4];
                a[mf][3] = sm[abase + mf * 320 + 164];
            }
#pragma unroll
            for (int nf = 0; nf < 4; nf++) {
                b[nf][0] = sm[bbase + nf * 160];
                b[nf][1] = sm[bbase + nf * 160 + 4];
            }
#pragma unroll
            for (int mf = 0; mf < 4; mf++)
#pragma unroll
                for (int nf = 0; nf < 4; nf++) mma16(c[mf][nf], a[mf], b[nf]);
        }
        if (ch < 7) {
            const uint32_t An = (ch & 1) ? GA0 : GA1;
            const uint32_t Bn = (ch & 1) ? GB0 : GB1;
#pragma unroll
            for (int i = 0; i < 4; i++) {
                int idx = tid + i * 256;
                int r = idx >> 3, c4 = idx & 7;
                uint2 ha = make_uint2(pk2(av[i].x, av[i].y), pk2(av[i].z, av[i].w));
                uint2 hb = make_uint2(pk2(bv[i].x, bv[i].y), pk2(bv[i].z, bv[i].w));
                *(uint2*)&sm[An + r * 20 + c4 * 2] = ha;
                *(uint2*)&sm[Bn + r * 20 + c4 * 2] = hb;
            }
            __syncthreads();
        }
    }

    // epilogue
#pragma unroll
    for (int nf = 0; nf < 4; nf++) {
        const int col = n0 + wn * 32 + nf * 8 + 2 * (lane & 3);
        const float bi0 = bias[col], bi1 = bias[col + 1];
#pragma unroll
        for (int mf = 0; mf < 4; mf++) {
            const int row = m0 + wm * 64 + mf * 16 + (lane >> 2);
            size_t o0 = (size_t)row * CC + col;
            size_t o1 = (size_t)(row + 8) * CC + col;
            float2 v0, v1;
            v0.x = c[mf][nf][0] + bi0; v0.y = c[mf][nf][1] + bi1;
            v1.x = c[mf][nf][2] + bi0; v1.y = c[mf][nf][3] + bi1;
            if (resid) {
                float2 r0 = *(const float2*)(resid + o0);
                float2 r1 = *(const float2*)(resid + o1);
                v0.x += r0.x; v0.y += r0.y;
                v1.x += r1.x; v1.y += r1.y;
            }
            *(float2*)(out + o0) = v0;
            *(float2*)(out + o1) = v1;
        }
    }
}

// ================= landmark softmax via fp16 mma: P = softmax(src.sel^T/16) =================
// grid (128, 2): y picks (q,Pq) or (k,Pk). Gathers sel rows directly via g_selidx.
// SEL: 40 rows x 128 kpairs, stride 132 u32. A buffers as gemm (stride 20).
#define LSEL 0u
#define LA0 5280u
#define LA1 7840u
#define L_SMEM (10400u * 4u)

__global__ __launch_bounds__(256) void lm_mma() {
    extern __shared__ __align__(16) uint32_t sm[];
    const int tid = threadIdx.x, lane = tid & 31, wid = tid >> 5;
    const int m0 = blockIdx.x * 128;
    const int b = m0 >> 13;
    const float* src = blockIdx.y ? g_k : g_q;
    float* P = blockIdx.y ? g_Pk : g_Pq;

    // gather + convert sel (40 rows of k) into smem
#pragma unroll
    for (int i = 0; i < 10; i++) {
        int idx = tid + i * 256;
        int r = idx >> 6, c4 = idx & 63;
        const float* rp = g_k + ((size_t)b * NN + g_selidx[b * KK + r]) * CC;
        float4 v = *(const float4*)(rp + c4 * 4);
        uint2 h = make_uint2(pk2(v.x, v.y), pk2(v.z, v.w));
        *(uint2*)&sm[LSEL + r * 132 + c4 * 2] = h;
    }
    // prefetch A chunk 0
    float4 av[4];
#pragma unroll
    for (int i = 0; i < 4; i++) {
        int idx = tid + i * 256;
        int r = idx >> 3, c4 = idx & 7;
        av[i] = *(const float4*)(src + (size_t)(m0 + r) * CC + c4 * 4);
    }
#pragma unroll
    for (int i = 0; i < 4; i++) {
        int idx = tid + i * 256;
        int r = idx >> 3, c4 = idx & 7;
        uint2 ha = make_uint2(pk2(av[i].x, av[i].y), pk2(av[i].z, av[i].w));
        *(uint2*)&sm[LA0 + r * 20 + c4 * 2] = ha;
    }
    __syncthreads();

    float c[5][4];
#pragma unroll
    for (int nf = 0; nf < 5; nf++)
#pragma unroll
        for (int j = 0; j < 4; j++) c[nf][j] = 0.f;

    for (int ch = 0; ch < 8; ch++) {
        if (ch < 7) {
            int k0 = (ch + 1) * 32;
#pragma unroll
            for (int i = 0; i < 4; i++) {
                int idx = tid + i * 256;
                int r = idx >> 3, c4 = idx & 7;
                av[i] = *(const float4*)(src + (size_t)(m0 + r) * CC + k0 + c4 * 4);
            }
        }
        const uint32_t Ab = (ch & 1) ? LA1 : LA0;
#pragma unroll
        for (int s = 0; s < 2; s++) {
            const uint32_t abase = Ab + (wid * 16 + (lane >> 2)) * 20 + (lane & 3) + s * 8;
            const uint32_t sbase = LSEL + (lane >> 2) * 132 + (lane & 3) + ch * 16 + s * 8;
            uint32_t a[4], bfr[5][2];
            a[0] = sm[abase];
            a[1] = sm[abase + 160];
            a[2] = sm[abase + 4];
            a[3] = sm[abase + 164];
#pragma unroll
            for (int nf = 0; nf < 5; nf++) {
                bfr[nf][0] = sm[sbase + nf * 8 * 132];
                bfr[nf][1] = sm[sbase + nf * 8 * 132 + 4];
            }
#pragma unroll
            for (int nf = 0; nf < 5; nf++) mma16(c[nf], a, bfr[nf]);
        }
        if (ch < 7) {
            const uint32_t An = (ch & 1) ? LA0 : LA1;
#pragma unroll
            for (int i = 0; i < 4; i++) {
                int idx = tid + i * 256;
                int r = idx >> 3, c4 = idx & 7;
                uint2 ha = make_uint2(pk2(av[i].x, av[i].y), pk2(av[i].z, av[i].w));
                *(uint2*)&sm[An + r * 20 + c4 * 2] = ha;
            }
            __syncthreads();
        }
    }

    // softmax epilogue: rows r0 = m0 + wid*16 + (lane>>2), r1 = r0+8
    float v0[10], v1[10];
#pragma unroll
    for (int nf = 0; nf < 5; nf++) {
        v0[nf * 2] = c[nf][0]; v0[nf * 2 + 1] = c[nf][1];
        v1[nf * 2] = c[nf][2]; v1[nf * 2 + 1] = c[nf][3];
    }
    float mx0 = v0[0], mx1 = v1[0];
#pragma unroll
    for (int i = 1; i < 10; i++) { mx0 = fmaxf(mx0, v0[i]); mx1 = fmaxf(mx1, v1[i]); }
    mx0 = fmaxf(mx0, __shfl_xor_sync(0xFFFFFFFFu, mx0, 1));
    mx0 = fmaxf(mx0, __shfl_xor_sync(0xFFFFFFFFu, mx0, 2));
    mx1 = fmaxf(mx1, __shfl_xor_sync(0xFFFFFFFFu, mx1, 1));
    mx1 = fmaxf(mx1, __shfl_xor_sync(0xFFFFFFFFu, mx1, 2));
    float s0 = 0.f, s1 = 0.f;
#pragma unroll
    for (int i = 0; i < 10; i++) {
        v0[i] = __expf((v0[i] - mx0) * 0.0625f); s0 += v0[i];
        v1[i] = __expf((v1[i] - mx1) * 0.0625f); s1 += v1[i];
    }
    s0 += __shfl_xor_sync(0xFFFFFFFFu, s0, 1);
    s0 += __shfl_xor_sync(0xFFFFFFFFu, s0, 2);
    s1 += __shfl_xor_sync(0xFFFFFFFFu, s1, 1);
    s1 += __shfl_xor_sync(0xFFFFFFFFu, s1, 2);
    const float i0 = 1.f / s0, i1 = 1.f / s1;
    const int r0 = m0 + wid * 16 + (lane >> 2);
#pragma unroll
    for (int nf = 0; nf < 5; nf++) {
        int col = nf * 8 + 2 * (lane & 3);
        float2 w0, w1;
        w0.x = v0[nf * 2] * i0; w0.y = v0[nf * 2 + 1] * i0;
        w1.x = v1[nf * 2] * i1; w1.y = v1[nf * 2 + 1] * i1;
        *(float2*)&P[(size_t)r0 * KK + col] = w0;
        *(float2*)&P[(size_t)(r0 + 8) * KK + col] = w1;
    }
}

// ================= T accumulate / output product =================
__global__ __launch_bounds__(256) void tacc_kernel() {
    __shared__ float P_sh[128 * KK];
    int b = blockIdx.y;
    int n0 = blockIdx.x * 128;
    int c = threadIdx.x;
    const float* Pg = &g_Pk[((size_t)b * NN + n0) * KK];
    for (int i = c * 4; i < 128 * KK; i += 1024)
        *(float4*)&P_sh[i] = *(const float4*)&Pg[i];
    __syncthreads();
    float acc[KK];
#pragma unroll
    for (int j = 0; j < KK; j++) acc[j] = 0.f;
    const float* v = &g_v[((size_t)b * NN + n0) * CC + c];
    for (int n = 0; n < 128; n++) {
        float val = v[(size_t)n * CC];
        const float* pr = &P_sh[n * KK];
#pragma unroll
        for (int j = 0; j < KK; j += 4) {
            float4 p = *(const float4*)&pr[j];
            acc[j + 0] += p.x * val; acc[j + 1] += p.y * val;
            acc[j + 2] += p.z * val; acc[j + 3] += p.w * val;
        }
    }
    float* T = &g_T[(size_t)b * KK * CC + c];
#pragma unroll
    for (int j = 0; j < KK; j++) atomicAdd(&T[j * CC], acc[j]);
}

__global__ __launch_bounds__(256) void out_kernel() {
    __shared__ float P_sh[128 * KK];
    int b = blockIdx.y;
    int n0 = blockIdx.x * 128;
    int c = threadIdx.x;
    const float* Pg = &g_Pq[((size_t)b * NN + n0) * KK];
    for (int i = c * 4; i < 128 * KK; i += 1024)
        *(float4*)&P_sh[i] = *(const float4*)&Pg[i];
    float t[KK];
    const float* T = &g_T[(size_t)b * KK * CC + c];
#pragma unroll
    for (int j = 0; j < KK; j++) t[j] = T[j * CC];
    __syncthreads();
    float* o = &g_attn[((size_t)b * NN + n0) * CC + c];
    for (int n = 0; n < 128; n++) {
        const float* pr = &P_sh[n * KK];
        float s = 0.f;
#pragma unroll
        for (int j = 0; j < KK; j += 4) {
            float4 p = *(const float4*)&pr[j];
            s += p.x * t[j + 0] + p.y * t[j + 1] + p.z * t[j + 2] + p.w * t[j + 3];
        }
        o[(size_t)n * CC] = s;
    }
}

// ================= launch =================
extern "C" void kernel_launch(void* const* d_in, const int* in_sizes, int n_in,
                              void* d_out, int out_size) {
    (void)in_sizes; (void)n_in; (void)out_size;
    const float* query = (const float*)d_in[0];
    const float* Wq = (const float*)d_in[1];
    const float* bq = (const float*)d_in[2];
    const float* Wk = (const float*)d_in[3];
    const float* bk = (const float*)d_in[4];
    const float* Wv = (const float*)d_in[5];
    const float* bv = (const float*)d_in[6];
    const float* Wo = (const float*)d_in[7];
    const float* bo = (const float*)d_in[8];
    float* out = (float*)d_out;

    cudaFuncSetAttribute(gemm_mma, cudaFuncAttributeMaxDynamicSharedMemorySize, G_SMEM);
    cudaFuncSetAttribute(lm_mma, cudaFuncAttributeMaxDynamicSharedMemorySize, L_SMEM);

    float *p_q, *p_k, *p_v, *p_attn;
    cudaGetSymbolAddress((void**)&p_q, g_q);
    cudaGetSymbolAddress((void**)&p_k, g_k);
    cudaGetSymbolAddress((void**)&p_v, g_v);
    cudaGetSymbolAddress((void**)&p_attn, g_attn);

    xsum_kernel<<<64, 256>>>(query);
    prep_kernel<<<BB, 256>>>(Wq, bq, Wk);
    score_kernel<<<MM / 8, 256>>>(query);
    topk_kernel<<<BB * 32, 256>>>();

    // fused q/k/v projections
    dim3 gqkv(MM / 128, CC / 128, 3);
    gemm_mma<<<gqkv, 256, G_SMEM>>>(query, Wq, Wk, Wv, bq, bk, bv, nullptr, p_q, p_k, p_v);

    // fused landmark softmax for q and k (gathers sel rows directly)
    lm_mma<<<dim3(MM / 128, 2), 256, L_SMEM>>>();

    dim3 gt(NN / 128, BB);
    tacc_kernel<<<gt, 256>>>();
    out_kernel<<<gt, 256>>>();

    // output projection + residual
    dim3 go(MM / 128, CC / 128, 1);
    gemm_mma<<<go, 256, G_SMEM>>>(p_attn, Wo, Wo, Wo, bo, bo, bo, query, out, out, out);
}

// round 5
// speedup vs baseline: 2.4226x; 1.1946x over previous
#include <cuda_runtime.h>
#include <cuda_fp16.h>
#include <cstdint>

#define BB 2
#define NN 8192
#define CC 256
#define KK 40
#define MM (BB * NN)

// ================= scratch =================
__device__ float g_q[MM * CC];
__device__ float g_k[MM * CC];
__device__ float g_v[MM * CC];
__device__ float g_attn[MM * CC];
__device__ float g_part[BB * 32 * CC];
__device__ float g_u[BB * CC];
__device__ float g_score[BB * NN];
__device__ int   g_selidx[BB * KK];
__device__ float g_T[BB * KK * CC];
__device__ float g_Pq[MM * KK];
__device__ float g_Pk[MM * KK];

// ================= helpers (family-portable PTX only) =================
__device__ __forceinline__ uint32_t pk2(float lo, float hi) {
    __half2 h = __floats2half2_rn(lo, hi);
    return *reinterpret_cast<uint32_t*>(&h);
}
__device__ __forceinline__ void mma16(float* c, const uint32_t* a, const uint32_t* b) {
    asm volatile(
        "mma.sync.aligned.m16n8k16.row.col.f32.f16.f16.f32 "
        "{%0,%1,%2,%3}, {%4,%5,%6,%7}, {%8,%9}, {%0,%1,%2,%3};"
        : "+f"(c[0]), "+f"(c[1]), "+f"(c[2]), "+f"(c[3])
        : "r"(a[0]), "r"(a[1]), "r"(a[2]), "r"(a[3]), "r"(b[0]), "r"(b[1]));
}

// ================= xsum: per-chunk partial column sums + zero g_T =================
__global__ __launch_bounds__(256) void xsum_kernel(const float* __restrict__ x) {
    __shared__ float4 red[4][64];
    int b = blockIdx.x >> 5, chunk = blockIdx.x & 31;
    int c4 = threadIdx.x & 63, rl = threadIdx.x >> 6;
    const float* base = x + ((size_t)b * NN + chunk * 256 + rl) * CC + c4 * 4;
    float4 s = make_float4(0.f, 0.f, 0.f, 0.f);
#pragma unroll 8
    for (int n = 0; n < 64; n++) {
        float4 v = *(const float4*)(base + (size_t)n * 4 * CC);
        s.x += v.x; s.y += v.y; s.z += v.z; s.w += v.w;
    }
    red[rl][c4] = s;
    for (int i = blockIdx.x * 256 + threadIdx.x; i < BB * KK * CC; i += 64 * 256)
        g_T[i] = 0.f;
    __syncthreads();
    if (rl == 0) {
        float4 a = red[0][c4], b2 = red[1][c4], c2 = red[2][c4], d = red[3][c4];
        float4 o;
        o.x = a.x + b2.x + c2.x + d.x; o.y = a.y + b2.y + c2.y + d.y;
        o.z = a.z + b2.z + c2.z + d.z; o.w = a.w + b2.w + c2.w + d.w;
        *(float4*)&g_part[(size_t)(b * 32 + chunk) * CC + c4 * 4] = o;
    }
}

// qsum = Wq*xsum + N*bq (fp32 exact), then u = Wk^T * qsum
__global__ void prep_kernel(const float* __restrict__ Wq, const float* __restrict__ bq,
                            const float* __restrict__ Wk) {
    __shared__ float xs[CC], qs[CC];
    int b = blockIdx.x, tid = threadIdx.x, w = tid >> 5, lane = tid & 31;
    float sx = 0.f;
#pragma unroll 8
    for (int ch = 0; ch < 32; ch++) sx += g_part[(size_t)(b * 32 + ch) * CC + tid];
    xs[tid] = sx;
    __syncthreads();
    for (int c = w * 32; c < w * 32 + 32; c++) {
        const float* wr = Wq + (size_t)c * CC;
        float s = 0.f;
#pragma unroll
        for (int i = 0; i < 8; i++) s += xs[lane + 32 * i] * wr[lane + 32 * i];
#pragma unroll
        for (int o = 16; o; o >>= 1) s += __shfl_xor_sync(0xFFFFFFFFu, s, o);
        if (lane == 0) qs[c] = s + (float)NN * bq[c];
    }
    __syncthreads();
    int c = tid;
    float u = 0.f;
#pragma unroll 8
    for (int d = 0; d < CC; d++) u += qs[d] * Wk[(size_t)d * CC + c];
    g_u[b * CC + c] = u;
}

// score_m = u_b . x_m  (order-identical to qsum.k_m/16 up to constant; exact fp32)
__global__ void score_kernel(const float* __restrict__ x) {
    int warp = threadIdx.x >> 5, lane = threadIdx.x & 31;
    int row = blockIdx.x * 8 + warp;
    int b = row >> 13;
    const float4* xr = (const float4*)(x + (size_t)row * CC);
    const float4* u = (const float4*)(&g_u[b * CC]);
    float4 v0 = xr[lane], v1 = xr[lane + 32];
    float4 u0 = u[lane], u1 = u[lane + 32];
    float s = v0.x * u0.x + v0.y * u0.y + v0.z * u0.z + v0.w * u0.w
            + v1.x * u1.x + v1.y * u1.y + v1.z * u1.z + v1.w * u1.w;
#pragma unroll
    for (int o = 16; o; o >>= 1) s += __shfl_xor_sync(0xFFFFFFFFu, s, o);
    if (lane == 0) g_score[row] = s;
}

// ================= exact top-40 via radix-256 select (one CTA per batch) =================
// Order of g_selidx is irrelevant downstream (softmax+contract is permutation-invariant);
// tie-break at the threshold value keeps exact lax.top_k semantics (smallest indices win).
__global__ __launch_bounds__(1024) void topk_kernel() {
    __shared__ uint32_t su[NN];       // 32 KB ordered keys
    __shared__ int hist[256];
    __shared__ int c_hi_sh, bin_sh, cnt;
    const int b = blockIdx.x, tid = threadIdx.x;

    for (int i = tid; i < NN; i += 1024) {
        uint32_t u = __float_as_uint(g_score[b * NN + i]);
        su[i] = (u & 0x80000000u) ? ~u : (u | 0x80000000u);
    }
    if (tid == 0) cnt = 0;

    uint32_t prefix = 0;
    int K_rem = KK;
#pragma unroll
    for (int shift = 24; shift >= 0; shift -= 8) {
        __syncthreads();
        if (tid < 256) hist[tid] = 0;
        __syncthreads();
        const uint32_t mask_hi = (shift == 24) ? 0u : (0xFFFFFFFFu << (shift + 8));
        for (int i = tid; i < NN; i += 1024) {
            uint32_t u = su[i];
            if ((u & mask_hi) == prefix) atomicAdd(&hist[(u >> shift) & 0xFF], 1);
        }
        __syncthreads();
        if (tid == 0) {
            int cum = 0, bin = 255;
            for (; bin > 0; bin--) {
                if (cum + hist[bin] >= K_rem) break;
                cum += hist[bin];
            }
            c_hi_sh = cum;
            bin_sh = bin;
        }
        __syncthreads();
        K_rem -= c_hi_sh;
        prefix |= ((uint32_t)bin_sh) << shift;
    }
    __syncthreads();

    const uint32_t u_thr = prefix;   // value of the 40th-largest score
    for (int i = tid; i < NN; i += 1024) {
        uint32_t u = su[i];
        if (u > u_thr) {
            int slot = atomicAdd(&cnt, 1);
            g_selidx[b * KK + slot] = i;
        } else if (u == u_thr) {
            int r = 0;                // rank among equal values by index
            for (int j = 0; j < i; j++) r += (su[j] == u_thr);
            if (r < K_rem) {
                int slot = atomicAdd(&cnt, 1);
                g_selidx[b * KK + slot] = i;
            }
        }
    }
}

// ================= fp16 mma GEMM: out[m,n] = X[m,:].W[n,:] + bias[n] (+resid) =================
#define GA0 0u
#define GA1 2560u
#define GB0 5120u
#define GB1 7680u
#define G_SMEM (10240u * 4u)

__global__ __launch_bounds__(256) void gemm_mma(
    const float* __restrict__ X,
    const float* __restrict__ W0, const float* __restrict__ W1, const float* __restrict__ W2,
    const float* __restrict__ B0, const float* __restrict__ B1, const float* __restrict__ B2,
    const float* __restrict__ resid,
    float* __restrict__ O0, float* __restrict__ O1, float* __restrict__ O2) {
    extern __shared__ __align__(16) uint32_t sm[];
    const int z = blockIdx.z;
    const float* W = (z == 0) ? W0 : (z == 1) ? W1 : W2;
    const float* bias = (z == 0) ? B0 : (z == 1) ? B1 : B2;
    float* out = (z == 0) ? O0 : (z == 1) ? O1 : O2;

    const int tid = threadIdx.x, lane = tid & 31, wid = tid >> 5;
    const int m0 = blockIdx.x * 128;
    const int n0 = blockIdx.y * 128;
    const int wm = wid & 1, wn = wid >> 1;

    float c[4][4][4];
#pragma unroll
    for (int mf = 0; mf < 4; mf++)
#pragma unroll
        for (int nf = 0; nf < 4; nf++)
#pragma unroll
            for (int j = 0; j < 4; j++) c[mf][nf][j] = 0.f;

    float4 av[4], bv[4];
#pragma unroll
    for (int i = 0; i < 4; i++) {
        int idx = tid + i * 256;
        int r = idx >> 3, c4 = idx & 7;
        av[i] = *(const float4*)(X + (size_t)(m0 + r) * CC + c4 * 4);
        bv[i] = *(const float4*)(W + (size_t)(n0 + r) * CC + c4 * 4);
    }
#pragma unroll
    for (int i = 0; i < 4; i++) {
        int idx = tid + i * 256;
        int r = idx >> 3, c4 = idx & 7;
        uint2 ha = make_uint2(pk2(av[i].x, av[i].y), pk2(av[i].z, av[i].w));
        uint2 hb = make_uint2(pk2(bv[i].x, bv[i].y), pk2(bv[i].z, bv[i].w));
        *(uint2*)&sm[GA0 + r * 20 + c4 * 2] = ha;
        *(uint2*)&sm[GB0 + r * 20 + c4 * 2] = hb;
    }
    __syncthreads();

    for (int ch = 0; ch < 8; ch++) {
        if (ch < 7) {
            int k0 = (ch + 1) * 32;
#pragma unroll
            for (int i = 0; i < 4; i++) {
                int idx = tid + i * 256;
                int r = idx >> 3, c4 = idx & 7;
                av[i] = *(const float4*)(X + (size_t)(m0 + r) * CC + k0 + c4 * 4);
                bv[i] = *(const float4*)(W + (size_t)(n0 + r) * CC + k0 + c4 * 4);
            }
        }
        const uint32_t Ab = (ch & 1) ? GA1 : GA0;
        const uint32_t Bb = (ch & 1) ? GB1 : GB0;
#pragma unroll
        for (int s = 0; s < 2; s++) {
            const uint32_t abase = Ab + (wm * 64 + (lane >> 2)) * 20 + (lane & 3) + s * 8;
            const uint32_t bbase = Bb + (wn * 32 + (lane >> 2)) * 20 + (lane & 3) + s * 8;
            uint32_t a[4][4], b[4][2];
#pragma unroll
            for (int mf = 0; mf < 4; mf++) {
                a[mf][0] = sm[abase + mf * 320];
                a[mf][1] = sm[abase + mf * 320 + 160];
                a[mf][2] = sm[abase + mf * 320 + 4];
                a[mf][3] = sm[abase + mf * 320 + 164];
            }
#pragma unroll
            for (int nf = 0; nf < 4; nf++) {
                b[nf][0] = sm[bbase + nf * 160];
                b[nf][1] = sm[bbase + nf * 160 + 4];
            }
#pragma unroll
            for (int mf = 0; mf < 4; mf++)
#pragma unroll
                for (int nf = 0; nf < 4; nf++) mma16(c[mf][nf], a[mf], b[nf]);
        }
        if (ch < 7) {
            const uint32_t An = (ch & 1) ? GA0 : GA1;
            const uint32_t Bn = (ch & 1) ? GB0 : GB1;
#pragma unroll
            for (int i = 0; i < 4; i++) {
                int idx = tid + i * 256;
                int r = idx >> 3, c4 = idx & 7;
                uint2 ha = make_uint2(pk2(av[i].x, av[i].y), pk2(av[i].z, av[i].w));
                uint2 hb = make_uint2(pk2(bv[i].x, bv[i].y), pk2(bv[i].z, bv[i].w));
                *(uint2*)&sm[An + r * 20 + c4 * 2] = ha;
                *(uint2*)&sm[Bn + r * 20 + c4 * 2] = hb;
            }
            __syncthreads();
        }
    }

#pragma unroll
    for (int nf = 0; nf < 4; nf++) {
        const int col = n0 + wn * 32 + nf * 8 + 2 * (lane & 3);
        const float bi0 = bias[col], bi1 = bias[col + 1];
#pragma unroll
        for (int mf = 0; mf < 4; mf++) {
            const int row = m0 + wm * 64 + mf * 16 + (lane >> 2);
            size_t o0 = (size_t)row * CC + col;
            size_t o1 = (size_t)(row + 8) * CC + col;
            float2 v0, v1;
            v0.x = c[mf][nf][0] + bi0; v0.y = c[mf][nf][1] + bi1;
            v1.x = c[mf][nf][2] + bi0; v1.y = c[mf][nf][3] + bi1;
            if (resid) {
                float2 r0 = *(const float2*)(resid + o0);
                float2 r1 = *(const float2*)(resid + o1);
                v0.x += r0.x; v0.y += r0.y;
                v1.x += r1.x; v1.y += r1.y;
            }
            *(float2*)(out + o0) = v0;
            *(float2*)(out + o1) = v1;
        }
    }
}

// ================= landmark softmax via fp16 mma: P = softmax(src.sel^T/16) =================
#define LSEL 0u
#define LA0 5280u
#define LA1 7840u
#define L_SMEM (10400u * 4u)

__global__ __launch_bounds__(256) void lm_mma() {
    extern __shared__ __align__(16) uint32_t sm[];
    const int tid = threadIdx.x, lane = tid & 31, wid = tid >> 5;
    const int m0 = blockIdx.x * 128;
    const int b = m0 >> 13;
    const float* src = blockIdx.y ? g_k : g_q;
    float* P = blockIdx.y ? g_Pk : g_Pq;

#pragma unroll
    for (int i = 0; i < 10; i++) {
        int idx = tid + i * 256;
        int r = idx >> 6, c4 = idx & 63;
        const float* rp = g_k + ((size_t)b * NN + g_selidx[b * KK + r]) * CC;
        float4 v = *(const float4*)(rp + c4 * 4);
        uint2 h = make_uint2(pk2(v.x, v.y), pk2(v.z, v.w));
        *(uint2*)&sm[LSEL + r * 132 + c4 * 2] = h;
    }
    float4 av[4];
#pragma unroll
    for (int i = 0; i < 4; i++) {
        int idx = tid + i * 256;
        int r = idx >> 3, c4 = idx & 7;
        av[i] = *(const float4*)(src + (size_t)(m0 + r) * CC + c4 * 4);
    }
#pragma unroll
    for (int i = 0; i < 4; i++) {
        int idx = tid + i * 256;
        int r = idx >> 3, c4 = idx & 7;
        uint2 ha = make_uint2(pk2(av[i].x, av[i].y), pk2(av[i].z, av[i].w));
        *(uint2*)&sm[LA0 + r * 20 + c4 * 2] = ha;
    }
    __syncthreads();

    float c[5][4];
#pragma unroll
    for (int nf = 0; nf < 5; nf++)
#pragma unroll
        for (int j = 0; j < 4; j++) c[nf][j] = 0.f;

    for (int ch = 0; ch < 8; ch++) {
        if (ch < 7) {
            int k0 = (ch + 1) * 32;
#pragma unroll
            for (int i = 0; i < 4; i++) {
                int idx = tid + i * 256;
                int r = idx >> 3, c4 = idx & 7;
                av[i] = *(const float4*)(src + (size_t)(m0 + r) * CC + k0 + c4 * 4);
            }
        }
        const uint32_t Ab = (ch & 1) ? LA1 : LA0;
#pragma unroll
        for (int s = 0; s < 2; s++) {
            const uint32_t abase = Ab + (wid * 16 + (lane >> 2)) * 20 + (lane & 3) + s * 8;
            const uint32_t sbase = LSEL + (lane >> 2) * 132 + (lane & 3) + ch * 16 + s * 8;
            uint32_t a[4], bfr[5][2];
            a[0] = sm[abase];
            a[1] = sm[abase + 160];
            a[2] = sm[abase + 4];
            a[3] = sm[abase + 164];
#pragma unroll
            for (int nf = 0; nf < 5; nf++) {
                bfr[nf][0] = sm[sbase + nf * 8 * 132];
                bfr[nf][1] = sm[sbase + nf * 8 * 132 + 4];
            }
#pragma unroll
            for (int nf = 0; nf < 5; nf++) mma16(c[nf], a, bfr[nf]);
        }
        if (ch < 7) {
            const uint32_t An = (ch & 1) ? LA0 : LA1;
#pragma unroll
            for (int i = 0; i < 4; i++) {
                int idx = tid + i * 256;
                int r = idx >> 3, c4 = idx & 7;
                uint2 ha = make_uint2(pk2(av[i].x, av[i].y), pk2(av[i].z, av[i].w));
                *(uint2*)&sm[An + r * 20 + c4 * 2] = ha;
            }
            __syncthreads();
        }
    }

    float v0[10], v1[10];
#pragma unroll
    for (int nf = 0; nf < 5; nf++) {
        v0[nf * 2] = c[nf][0]; v0[nf * 2 + 1] = c[nf][1];
        v1[nf * 2] = c[nf][2]; v1[nf * 2 + 1] = c[nf][3];
    }
    float mx0 = v0[0], mx1 = v1[0];
#pragma unroll
    for (int i = 1; i < 10; i++) { mx0 = fmaxf(mx0, v0[i]); mx1 = fmaxf(mx1, v1[i]); }
    mx0 = fmaxf(mx0, __shfl_xor_sync(0xFFFFFFFFu, mx0, 1));
    mx0 = fmaxf(mx0, __shfl_xor_sync(0xFFFFFFFFu, mx0, 2));
    mx1 = fmaxf(mx1, __shfl_xor_sync(0xFFFFFFFFu, mx1, 1));
    mx1 = fmaxf(mx1, __shfl_xor_sync(0xFFFFFFFFu, mx1, 2));
    float s0 = 0.f, s1 = 0.f;
#pragma unroll
    for (int i = 0; i < 10; i++) {
        v0[i] = __expf((v0[i] - mx0) * 0.0625f); s0 += v0[i];
        v1[i] = __expf((v1[i] - mx1) * 0.0625f); s1 += v1[i];
    }
    s0 += __shfl_xor_sync(0xFFFFFFFFu, s0, 1);
    s0 += __shfl_xor_sync(0xFFFFFFFFu, s0, 2);
    s1 += __shfl_xor_sync(0xFFFFFFFFu, s1, 1);
    s1 += __shfl_xor_sync(0xFFFFFFFFu, s1, 2);
    const float i0 = 1.f / s0, i1 = 1.f / s1;
    const int r0 = m0 + wid * 16 + (lane >> 2);
#pragma unroll
    for (int nf = 0; nf < 5; nf++) {
        int col = nf * 8 + 2 * (lane & 3);
        float2 w0, w1;
        w0.x = v0[nf * 2] * i0; w0.y = v0[nf * 2 + 1] * i0;
        w1.x = v1[nf * 2] * i1; w1.y = v1[nf * 2 + 1] * i1;
        *(float2*)&P[(size_t)r0 * KK + col] = w0;
        *(float2*)&P[(size_t)(r0 + 8) * KK + col] = w1;
    }
}

// ================= T accumulate / output product =================
__global__ __launch_bounds__(256) void tacc_kernel() {
    __shared__ float P_sh[128 * KK];
    int b = blockIdx.y;
    int n0 = blockIdx.x * 128;
    int c = threadIdx.x;
    const float* Pg = &g_Pk[((size_t)b * NN + n0) * KK];
    for (int i = c * 4; i < 128 * KK; i += 1024)
        *(float4*)&P_sh[i] = *(const float4*)&Pg[i];
    __syncthreads();
    float acc[KK];
#pragma unroll
    for (int j = 0; j < KK; j++) acc[j] = 0.f;
    const float* v = &g_v[((size_t)b * NN + n0) * CC + c];
    for (int n = 0; n < 128; n++) {
        float val = v[(size_t)n * CC];
        const float* pr = &P_sh[n * KK];
#pragma unroll
        for (int j = 0; j < KK; j += 4) {
            float4 p = *(const float4*)&pr[j];
            acc[j + 0] += p.x * val; acc[j + 1] += p.y * val;
            acc[j + 2] += p.z * val; acc[j + 3] += p.w * val;
        }
    }
    float* T = &g_T[(size_t)b * KK * CC + c];
#pragma unroll
    for (int j = 0; j < KK; j++) atomicAdd(&T[j * CC], acc[j]);
}

__global__ __launch_bounds__(256) void out_kernel() {
    __shared__ float P_sh[128 * KK];
    int b = blockIdx.y;
    int n0 = blockIdx.x * 128;
    int c = threadIdx.x;
    const float* Pg = &g_Pq[((size_t)b * NN + n0) * KK];
    for (int i = c * 4; i < 128 * KK; i += 1024)
        *(float4*)&P_sh[i] = *(const float4*)&Pg[i];
    float t[KK];
    const float* T = &g_T[(size_t)b * KK * CC + c];
#pragma unroll
    for (int j = 0; j < KK; j++) t[j] = T[j * CC];
    __syncthreads();
    float* o = &g_attn[((size_t)b * NN + n0) * CC + c];
    for (int n = 0; n < 128; n++) {
        const float* pr = &P_sh[n * KK];
        float s = 0.f;
#pragma unroll
        for (int j = 0; j < KK; j += 4) {
            float4 p = *(const float4*)&pr[j];
            s += p.x * t[j + 0] + p.y * t[j + 1] + p.z * t[j + 2] + p.w * t[j + 3];
        }
        o[(size_t)n * CC] = s;
    }
}

// ================= launch =================
extern "C" void kernel_launch(void* const* d_in, const int* in_sizes, int n_in,
                              void* d_out, int out_size) {
    (void)in_sizes; (void)n_in; (void)out_size;
    const float* query = (const float*)d_in[0];
    const float* Wq = (const float*)d_in[1];
    const float* bq = (const float*)d_in[2];
    const float* Wk = (const float*)d_in[3];
    const float* bk = (const float*)d_in[4];
    const float* Wv = (const float*)d_in[5];
    const float* bv = (const float*)d_in[6];
    const float* Wo = (const float*)d_in[7];
    const float* bo = (const float*)d_in[8];
    float* out = (float*)d_out;

    cudaFuncSetAttribute(gemm_mma, cudaFuncAttributeMaxDynamicSharedMemorySize, G_SMEM);
    cudaFuncSetAttribute(lm_mma, cudaFuncAttributeMaxDynamicSharedMemorySize, L_SMEM);

    float *p_q, *p_k, *p_v, *p_attn;
    cudaGetSymbolAddress((void**)&p_q, g_q);
    cudaGetSymbolAddress((void**)&p_k, g_k);
    cudaGetSymbolAddress((void**)&p_v, g_v);
    cudaGetSymbolAddress((void**)&p_attn, g_attn);

    xsum_kernel<<<64, 256>>>(query);
    prep_kernel<<<BB, 256>>>(Wq, bq, Wk);
    score_kernel<<<MM / 8, 256>>>(query);
    topk_kernel<<<BB, 1024>>>();

    dim3 gqkv(MM / 128, CC / 128, 3);
    gemm_mma<<<gqkv, 256, G_SMEM>>>(query, Wq, Wk, Wv, bq, bk, bv, nullptr, p_q, p_k, p_v);

    lm_mma<<<dim3(MM / 128, 2), 256, L_SMEM>>>();

    dim3 gt(NN / 128, BB);
    tacc_kernel<<<gt, 256>>>();
    out_kernel<<<gt, 256>>>();

    dim3 go(MM / 128, CC / 128, 1);
    gemm_mma<<<go, 256, G_SMEM>>>(p_attn, Wo, Wo, Wo, bo, bo, bo, query, out, out, out);
}